// round 5
// baseline (speedup 1.0000x reference)
#include <cuda_runtime.h>
#include <math.h>

#define NB 2
#define NN 50000
#define NE 640000
#define FD 128
#define NOUT 16
#define MR (NB*NN)   // 100000 rows
#define SB 49        // scan blocks (49*1024 >= NN)

// ---------------- device scratch (allocation-free) ----------------
__device__ __align__(256) float g_dinv[NN];
__device__ __align__(256) float g_deg[NN];
__device__ __align__(256) int   g_cnt[NN];
__device__ __align__(256) int   g_cur[NN];
__device__ __align__(256) int   g_rowptr[NN + 1];
__device__ __align__(256) int   g_bsum[SB];
__device__ __align__(256) int   g_boff[SB];
__device__ __align__(256) int   g_esrc[NE];     // src ids sorted by dst
__device__ __align__(256) float g_enorm[NE];    // norm sorted by dst
__device__ __align__(256) float g_bufA[(size_t)MR*FD];   // xw / xw2
__device__ __align__(256) float g_bufH[(size_t)MR*FD];   // relu(aggregated h)
__device__ __align__(256) float g_stats[512];            // sum/sumsq for 2 layers
__device__ __align__(256) float g_W2p[FD*FD];            // a1 ⊙ W2
__device__ __align__(256) float g_cw2[FD];               // c1 @ W2
__device__ __align__(256) float g_Wcp[FD*NOUT];          // a2 ⊙ Wc
__device__ __align__(256) float g_bcp[NOUT];             // bc + c2 @ Wc

// ---------------- prep: init, degree+histogram, dinv ----------------
__global__ void k_init() {
    int i = blockIdx.x*blockDim.x + threadIdx.x;
    if (i < NN) { g_deg[i] = 1.0f; g_cnt[i] = 0; }   // self-loop weight = 1
    if (i < 512) g_stats[i] = 0.0f;
}

__global__ void k_deghist(const int* __restrict__ ei, const float* __restrict__ ewp) {
    int e = blockIdx.x*blockDim.x + threadIdx.x;
    if (e >= NE) return;
    int dst = ei[NE + e];
    atomicAdd(&g_deg[dst], expf(ewp[e]));
    atomicAdd(&g_cnt[dst], 1);
}

__global__ void k_dinv() {
    int i = blockIdx.x*blockDim.x + threadIdx.x;
    if (i < NN) g_dinv[i] = rsqrtf(g_deg[i]);   // deg >= 1 always
}

// ---------------- parallel 3-phase exclusive scan over g_cnt ----------------
__global__ __launch_bounds__(1024) void k_scan1() {
    __shared__ int sh[1024];
    const int t = threadIdx.x;
    const int i = blockIdx.x * 1024 + t;
    int v = (i < NN) ? g_cnt[i] : 0;
    sh[t] = v;
    __syncthreads();
    #pragma unroll
    for (int off = 1; off < 1024; off <<= 1) {
        int x = (t >= off) ? sh[t - off] : 0;
        __syncthreads();
        sh[t] += x;
        __syncthreads();
    }
    if (i < NN) g_rowptr[i] = sh[t] - v;        // local exclusive prefix
    if (t == 1023) g_bsum[blockIdx.x] = sh[1023];
}

__global__ void k_scan2() {
    __shared__ int s[SB];
    int t = threadIdx.x;   // 64 threads
    if (t < SB) s[t] = g_bsum[t];
    __syncthreads();
    if (t == 0) {
        int run = 0;
        for (int i = 0; i < SB; i++) { int v = s[i]; s[i] = run; run += v; }
    }
    __syncthreads();
    if (t < SB) g_boff[t] = s[t];
}

__global__ __launch_bounds__(1024) void k_scan3() {
    const int i = blockIdx.x * 1024 + threadIdx.x;
    if (i < NN) {
        int v = g_rowptr[i] + g_boff[blockIdx.x];
        g_rowptr[i] = v;
        g_cur[i]    = v;
    }
    if (i == 0) g_rowptr[NN] = NE;
}

// ---------------- fill CSR buckets (src + norm, sorted by dst) ----------------
__global__ void k_fill(const int* __restrict__ ei, const float* __restrict__ ewp) {
    int e = blockIdx.x*blockDim.x + threadIdx.x;
    if (e >= NE) return;
    int src = ei[e], dst = ei[NE + e];
    int p = atomicAdd(&g_cur[dst], 1);
    g_esrc[p]  = src;
    g_enorm[p] = g_dinv[src] * expf(ewp[e]) * g_dinv[dst];
}

// ---------------- 3xTF32 tensor-core GEMM (fp32-grade accuracy) ----------------
// C[MR,128] = A[MR,128] @ B[128,128] (+ biasRow)
__device__ __forceinline__ unsigned f2tf(float f) {
    unsigned r;
    asm("cvt.rna.tf32.f32 %0, %1;" : "=r"(r) : "f"(f));
    return r;
}
__device__ __forceinline__ void split_tf(float f, unsigned &hi, unsigned &lo) {
    hi = f2tf(f);
    lo = f2tf(f - __uint_as_float(hi));
}
#define MMA_TF32(C, A0,A1,A2,A3, B0,B1) \
    asm volatile( \
        "mma.sync.aligned.m16n8k8.row.col.f32.tf32.tf32.f32 " \
        "{%0,%1,%2,%3}, {%4,%5,%6,%7}, {%8,%9}, {%0,%1,%2,%3};" \
        : "+f"(C[0]), "+f"(C[1]), "+f"(C[2]), "+f"(C[3]) \
        : "r"(A0), "r"(A1), "r"(A2), "r"(A3), "r"(B0), "r"(B1))

__global__ __launch_bounds__(256) void k_gemm(const float* __restrict__ A,
                                              const float* __restrict__ B,
                                              float* __restrict__ C,
                                              const float* __restrict__ biasRow) {
    __shared__ unsigned Ah[128][12], Al[128][12];   // [m][k] stride-12 -> conflict-free
    __shared__ unsigned Bh[8][136],  Bl[8][136];    // [k][n] stride-136 -> conflict-free
    const int t    = threadIdx.x;
    const int warp = t >> 5;
    const int lane = t & 31;
    const int l4   = lane >> 2;        // 0..7
    const int lm4  = lane & 3;         // 0..3
    const int wr   = warp * 16;
    const long rowBase = (long)blockIdx.x * 128;

    float c[16][4];
    #pragma unroll
    for (int nt = 0; nt < 16; nt++) {
        int col = nt*8 + 2*lm4;
        float bv0 = biasRow ? biasRow[col]     : 0.f;
        float bv1 = biasRow ? biasRow[col + 1] : 0.f;
        c[nt][0] = bv0; c[nt][1] = bv1;
        c[nt][2] = bv0; c[nt][3] = bv1;
    }

    const int arow = t >> 1;
    const int ak   = (t & 1) * 4;
    long arg = rowBase + arow; if (arg >= MR) arg = MR - 1;
    const int bk = t >> 5;
    const int bn = (t & 31) * 4;

    // prefetch chunk 0
    float4 av = *(const float4*)(A + arg*FD + ak);
    float4 bv = *(const float4*)(B + (size_t)bk*FD + bn);

    for (int kc = 0; kc < 16; kc++) {
        // store current chunk (split hi/lo)
        unsigned h, l;
        split_tf(av.x, h, l); Ah[arow][ak+0] = h; Al[arow][ak+0] = l;
        split_tf(av.y, h, l); Ah[arow][ak+1] = h; Al[arow][ak+1] = l;
        split_tf(av.z, h, l); Ah[arow][ak+2] = h; Al[arow][ak+2] = l;
        split_tf(av.w, h, l); Ah[arow][ak+3] = h; Al[arow][ak+3] = l;
        split_tf(bv.x, h, l); Bh[bk][bn+0] = h; Bl[bk][bn+0] = l;
        split_tf(bv.y, h, l); Bh[bk][bn+1] = h; Bl[bk][bn+1] = l;
        split_tf(bv.z, h, l); Bh[bk][bn+2] = h; Bl[bk][bn+2] = l;
        split_tf(bv.w, h, l); Bh[bk][bn+3] = h; Bl[bk][bn+3] = l;
        __syncthreads();

        // prefetch next chunk while computing
        if (kc + 1 < 16) {
            av = *(const float4*)(A + arg*FD + (kc+1)*8 + ak);
            bv = *(const float4*)(B + (size_t)((kc+1)*8 + bk)*FD + bn);
        }

        unsigned ah0 = Ah[wr + l4    ][lm4    ];
        unsigned ah1 = Ah[wr + l4 + 8][lm4    ];
        unsigned ah2 = Ah[wr + l4    ][lm4 + 4];
        unsigned ah3 = Ah[wr + l4 + 8][lm4 + 4];
        unsigned al0 = Al[wr + l4    ][lm4    ];
        unsigned al1 = Al[wr + l4 + 8][lm4    ];
        unsigned al2 = Al[wr + l4    ][lm4 + 4];
        unsigned al3 = Al[wr + l4 + 8][lm4 + 4];
        #pragma unroll
        for (int nt = 0; nt < 16; nt++) {
            unsigned bh0 = Bh[lm4    ][nt*8 + l4];
            unsigned bh1 = Bh[lm4 + 4][nt*8 + l4];
            unsigned bl0 = Bl[lm4    ][nt*8 + l4];
            unsigned bl1 = Bl[lm4 + 4][nt*8 + l4];
            MMA_TF32(c[nt], al0,al1,al2,al3, bh0,bh1);
            MMA_TF32(c[nt], ah0,ah1,ah2,ah3, bl0,bl1);
            MMA_TF32(c[nt], ah0,ah1,ah2,ah3, bh0,bh1);
        }
        __syncthreads();
    }

    long crow0 = rowBase + wr + l4;
    long crow1 = crow0 + 8;
    #pragma unroll
    for (int nt = 0; nt < 16; nt++) {
        int col = nt*8 + 2*lm4;
        if (crow0 < MR) *(float2*)(C + crow0*FD + col) = make_float2(c[nt][0], c[nt][1]);
        if (crow1 < MR) *(float2*)(C + crow1*FD + col) = make_float2(c[nt][2], c[nt][3]);
    }
}

// ---------------- CSR aggregation + fused ReLU + BN stats ----------------
// H[b,n] = relu(dinv[n]^2*A[b,n] + bias + sum_e norm[e]*A[b,src[e]]); stats += relu vals
__global__ __launch_bounds__(256) void k_agg(const float* __restrict__ A,
                                             float* __restrict__ H,
                                             const float* __restrict__ bias,
                                             int statoff) {
    __shared__ float ss[256];   // [0:128) sum, [128:256) sumsq
    int warp = threadIdx.x >> 5;
    int lane = threadIdx.x & 31;
    int n = blockIdx.x * 8 + warp;
    int b = blockIdx.y;
    ss[threadIdx.x] = 0.f;
    __syncthreads();

    if (n < NN) {
        const float4* Ab = (const float4*)(A + (size_t)b*NN*FD);
        float d = g_dinv[n];
        float sn = d * d;
        float4 v  = Ab[(size_t)n*32 + lane];
        float4 bvv = ((const float4*)bias)[lane];
        float4 acc;
        acc.x = fmaf(sn, v.x, bvv.x);
        acc.y = fmaf(sn, v.y, bvv.y);
        acc.z = fmaf(sn, v.z, bvv.z);
        acc.w = fmaf(sn, v.w, bvv.w);

        int j = g_rowptr[n];
        const int e = g_rowptr[n + 1];
        for (; j + 1 < e; j += 2) {
            int sA = g_esrc[j],   sB2 = g_esrc[j+1];
            float nA = g_enorm[j], nB = g_enorm[j+1];
            float4 vA = Ab[(size_t)sA*32 + lane];
            float4 vB = Ab[(size_t)sB2*32 + lane];
            acc.x = fmaf(nA, vA.x, acc.x); acc.y = fmaf(nA, vA.y, acc.y);
            acc.z = fmaf(nA, vA.z, acc.z); acc.w = fmaf(nA, vA.w, acc.w);
            acc.x = fmaf(nB, vB.x, acc.x); acc.y = fmaf(nB, vB.y, acc.y);
            acc.z = fmaf(nB, vB.z, acc.z); acc.w = fmaf(nB, vB.w, acc.w);
        }
        if (j < e) {
            int sA = g_esrc[j];
            float nA = g_enorm[j];
            float4 vA = Ab[(size_t)sA*32 + lane];
            acc.x = fmaf(nA, vA.x, acc.x); acc.y = fmaf(nA, vA.y, acc.y);
            acc.z = fmaf(nA, vA.z, acc.z); acc.w = fmaf(nA, vA.w, acc.w);
        }
        // ReLU, store, and accumulate stats in shared
        acc.x = fmaxf(acc.x, 0.f); acc.y = fmaxf(acc.y, 0.f);
        acc.z = fmaxf(acc.z, 0.f); acc.w = fmaxf(acc.w, 0.f);
        ((float4*)(H + ((size_t)b*NN + n)*FD))[lane] = acc;
        int f = lane * 4;
        atomicAdd(&ss[f+0], acc.x); atomicAdd(&ss[128+f+0], acc.x*acc.x);
        atomicAdd(&ss[f+1], acc.y); atomicAdd(&ss[128+f+1], acc.y*acc.y);
        atomicAdd(&ss[f+2], acc.z); atomicAdd(&ss[128+f+2], acc.z*acc.z);
        atomicAdd(&ss[f+3], acc.w); atomicAdd(&ss[128+f+3], acc.w*acc.w);
    }
    __syncthreads();
    if (threadIdx.x < 128) {
        atomicAdd(&g_stats[statoff + threadIdx.x],       ss[threadIdx.x]);
        atomicAdd(&g_stats[statoff + 128 + threadIdx.x], ss[128 + threadIdx.x]);
    }
}

// ---------------- fold BN1 into W2: W2' = a1⊙W2, cw2 = c1@W2 ----------------
__global__ void k_fin1(const float* __restrict__ W2, const float* __restrict__ g1,
                       const float* __restrict__ be1) {
    __shared__ float a[FD], c[FD];
    int t = threadIdx.x;   // 128
    float inv = 1.0f / (float)MR;
    float mu  = g_stats[t] * inv;
    float var = g_stats[128 + t] * inv - mu*mu;
    float av  = g1[t] * rsqrtf(var + 1e-5f);
    a[t] = av; c[t] = be1[t] - mu*av;
    __syncthreads();
    float acc = 0.f;
    for (int f = 0; f < FD; f++) {
        float w = W2[f*FD + t];
        g_W2p[f*FD + t] = a[f]*w;
        acc = fmaf(c[f], w, acc);
    }
    g_cw2[t] = acc;
}

// ---------------- fold BN2 into Wc: Wc' = a2⊙Wc, bc' = bc + c2@Wc ----------------
__global__ void k_fin2(const float* __restrict__ Wc, const float* __restrict__ bc,
                       const float* __restrict__ g2, const float* __restrict__ be2) {
    __shared__ float a[FD], c[FD];
    int t = threadIdx.x;   // 128
    float inv = 1.0f / (float)MR;
    float mu  = g_stats[256 + t] * inv;
    float var = g_stats[384 + t] * inv - mu*mu;
    float av  = g2[t] * rsqrtf(var + 1e-5f);
    a[t] = av; c[t] = be2[t] - mu*av;
    __syncthreads();
    if (t < NOUT) {
        float acc = bc[t];
        for (int f = 0; f < FD; f++) {
            float w = Wc[f*NOUT + t];
            g_Wcp[f*NOUT + t] = a[f]*w;
            acc = fmaf(c[f], w, acc);
        }
        g_bcp[t] = acc;
    }
}

// ---------------- output head: out = H @ Wc' + bc' (H already relu'd) ----------------
__global__ void k_out(float* __restrict__ out) {
    __shared__ float Ws[FD*NOUT];
    __shared__ float Hs[8][FD];
    int t = threadIdx.x;   // 128
    #pragma unroll
    for (int i = 0; i < 16; i++) Ws[i*128 + t] = g_Wcp[i*128 + t];
    long rb = (long)blockIdx.x * 8;
    #pragma unroll
    for (int i = 0; i < 8; i++) {
        long r = rb + i;
        Hs[i][t] = (r < MR) ? g_bufH[r*FD + t] : 0.f;
    }
    __syncthreads();
    int rl = t >> 4, c = t & 15;
    float acc = g_bcp[c];
    #pragma unroll 8
    for (int f = 0; f < FD; f++) acc = fmaf(Hs[rl][f], Ws[f*NOUT + c], acc);
    long r = rb + rl;
    if (r < MR) out[r*NOUT + c] = acc;
}

// ---------------- launcher ----------------
extern "C" void kernel_launch(void* const* d_in, const int* in_sizes, int n_in,
                              void* d_out, int out_size) {
    const float* x   = (const float*)d_in[0];
    const int*   ei  = (const int*)  d_in[1];
    const float* ewp = (const float*)d_in[2];
    const float* W1  = (const float*)d_in[3];
    const float* b1  = (const float*)d_in[4];
    const float* W2  = (const float*)d_in[5];
    const float* b2  = (const float*)d_in[6];
    const float* g1  = (const float*)d_in[7];
    const float* be1 = (const float*)d_in[8];
    const float* g2  = (const float*)d_in[9];
    const float* be2 = (const float*)d_in[10];
    const float* Wc  = (const float*)d_in[11];
    const float* bc  = (const float*)d_in[12];
    float* out = (float*)d_out;

    float *bufA, *bufH, *W2p, *cw2;
    cudaGetSymbolAddress((void**)&bufA, g_bufA);
    cudaGetSymbolAddress((void**)&bufH, g_bufH);
    cudaGetSymbolAddress((void**)&W2p,  g_W2p);
    cudaGetSymbolAddress((void**)&cw2,  g_cw2);

    const int gemmBlocks = (MR + 127) / 128;          // 782
    const dim3 aggGrid((NN + 7) / 8, NB);             // 6250 x 2

    // prep + CSR build (shared by both layers/batches)
    k_init<<<(NN + 255)/256, 256>>>();
    k_deghist<<<(NE + 255)/256, 256>>>(ei, ewp);
    k_dinv<<<(NN + 255)/256, 256>>>();
    k_scan1<<<SB, 1024>>>();
    k_scan2<<<1, 64>>>();
    k_scan3<<<SB, 1024>>>();
    k_fill<<<(NE + 255)/256, 256>>>(ei, ewp);

    // Layer 1
    k_gemm<<<gemmBlocks, 256>>>(x, W1, bufA, nullptr);
    k_agg<<<aggGrid, 256>>>(bufA, bufH, b1, 0);
    k_fin1<<<1, 128>>>(W2, g1, be1);

    // Layer 2 (H already relu'd; BN1 folded into W2p/cw2)
    k_gemm<<<gemmBlocks, 256>>>(bufH, W2p, bufA, cw2);
    k_agg<<<aggGrid, 256>>>(bufA, bufH, b2, 256);
    k_fin2<<<1, 128>>>(Wc, bc, g2, be2);

    // Head (H already relu'd; BN2 folded into Wcp/bcp)
    k_out<<<(MR + 7)/8, 128>>>(out);
}

// round 6
// speedup vs baseline: 1.1935x; 1.1935x over previous
#include <cuda_runtime.h>
#include <math.h>

#define NB 2
#define NN 50000
#define NE 640000
#define FD 128
#define NOUT 16
#define MR (NB*NN)   // 100000 rows
#define SB 49        // scan blocks (49*1024 >= NN)

// ---------------- device scratch (allocation-free) ----------------
__device__ __align__(256) float g_dinv[NN];
__device__ __align__(256) float g_deg[NN];
__device__ __align__(256) int   g_cnt[NN];
__device__ __align__(256) int   g_cur[NN];
__device__ __align__(256) int   g_rowptr[NN + 1];
__device__ __align__(256) int   g_bsum[SB];
__device__ __align__(256) int   g_boff[SB];
__device__ __align__(256) int   g_esrc[NE];     // src ids sorted by dst
__device__ __align__(256) float g_enorm[NE];    // norm sorted by dst
__device__ __align__(256) float g_bufA[(size_t)MR*FD];   // xw / xw2
__device__ __align__(256) float g_bufH[(size_t)MR*FD];   // relu(aggregated h)
__device__ __align__(256) float g_stats[512];            // sum/sumsq for 2 layers
__device__ __align__(256) float g_W2p[FD*FD];            // a1 ⊙ W2
__device__ __align__(256) float g_cw2[FD];               // c1 @ W2
__device__ __align__(256) float g_Wcp[FD*NOUT];          // a2 ⊙ Wc
__device__ __align__(256) float g_bcp[NOUT];             // bc + c2 @ Wc

// ---------------- prep: init, degree+histogram, dinv ----------------
__global__ void k_init() {
    int i = blockIdx.x*blockDim.x + threadIdx.x;
    if (i < NN) { g_deg[i] = 1.0f; g_cnt[i] = 0; }   // self-loop weight = 1
    if (i < 512) g_stats[i] = 0.0f;
}

__global__ void k_deghist(const int* __restrict__ ei, const float* __restrict__ ewp) {
    int e = blockIdx.x*blockDim.x + threadIdx.x;
    if (e >= NE) return;
    int dst = ei[NE + e];
    atomicAdd(&g_deg[dst], expf(ewp[e]));
    atomicAdd(&g_cnt[dst], 1);
}

__global__ void k_dinv() {
    int i = blockIdx.x*blockDim.x + threadIdx.x;
    if (i < NN) g_dinv[i] = rsqrtf(g_deg[i]);   // deg >= 1 always
}

// ---------------- parallel 3-phase exclusive scan over g_cnt ----------------
__global__ __launch_bounds__(1024) void k_scan1() {
    __shared__ int sh[1024];
    const int t = threadIdx.x;
    const int i = blockIdx.x * 1024 + t;
    int v = (i < NN) ? g_cnt[i] : 0;
    sh[t] = v;
    __syncthreads();
    #pragma unroll
    for (int off = 1; off < 1024; off <<= 1) {
        int x = (t >= off) ? sh[t - off] : 0;
        __syncthreads();
        sh[t] += x;
        __syncthreads();
    }
    if (i < NN) g_rowptr[i] = sh[t] - v;        // local exclusive prefix
    if (t == 1023) g_bsum[blockIdx.x] = sh[1023];
}

__global__ void k_scan2() {
    __shared__ int s[SB];
    int t = threadIdx.x;   // 64 threads
    if (t < SB) s[t] = g_bsum[t];
    __syncthreads();
    if (t == 0) {
        int run = 0;
        for (int i = 0; i < SB; i++) { int v = s[i]; s[i] = run; run += v; }
    }
    __syncthreads();
    if (t < SB) g_boff[t] = s[t];
}

__global__ __launch_bounds__(1024) void k_scan3() {
    const int i = blockIdx.x * 1024 + threadIdx.x;
    if (i < NN) {
        int v = g_rowptr[i] + g_boff[blockIdx.x];
        g_rowptr[i] = v;
        g_cur[i]    = v;
    }
    if (i == 0) g_rowptr[NN] = NE;
}

// ---------------- fill CSR buckets (src + norm, sorted by dst) ----------------
__global__ void k_fill(const int* __restrict__ ei, const float* __restrict__ ewp) {
    int e = blockIdx.x*blockDim.x + threadIdx.x;
    if (e >= NE) return;
    int src = ei[e], dst = ei[NE + e];
    int p = atomicAdd(&g_cur[dst], 1);
    g_esrc[p]  = src;
    g_enorm[p] = g_dinv[src] * expf(ewp[e]) * g_dinv[dst];
}

// ---------------- split-bf16 3-term tensor-core GEMM (near-fp32 accuracy) ----------------
// C[MR,128] = A[MR,128] @ B[128,128] (+ biasRow)
// a = ah + al (bf16 each, ~16 mantissa bits combined); D = al*bh + ah*bl + ah*bh
__device__ __forceinline__ void packbf(float f0, float f1, unsigned &hi, unsigned &lo) {
    // packed bf16x2: lower half = f0 (even k), upper half = f1 (odd k)
    asm("cvt.rn.bf16x2.f32 %0, %1, %2;" : "=r"(hi) : "f"(f1), "f"(f0));
    float h0 = __uint_as_float(hi << 16);
    float h1 = __uint_as_float(hi & 0xffff0000u);
    asm("cvt.rn.bf16x2.f32 %0, %1, %2;" : "=r"(lo) : "f"(f1 - h1), "f"(f0 - h0));
}
#define MMA_BF16(C, A0,A1,A2,A3, B0,B1) \
    asm volatile( \
        "mma.sync.aligned.m16n8k16.row.col.f32.bf16.bf16.f32 " \
        "{%0,%1,%2,%3}, {%4,%5,%6,%7}, {%8,%9}, {%0,%1,%2,%3};" \
        : "+f"(C[0]), "+f"(C[1]), "+f"(C[2]), "+f"(C[3]) \
        : "r"(A0), "r"(A1), "r"(A2), "r"(A3), "r"(B0), "r"(B1))

__global__ __launch_bounds__(256) void k_gemm(const float* __restrict__ A,
                                              const float* __restrict__ B,
                                              float* __restrict__ C,
                                              const float* __restrict__ biasRow) {
    __shared__ unsigned Ah[8][136], Al[8][136];   // [k2][m], stride 136 -> conflict-free frags
    __shared__ unsigned Bh[8][136], Bl[8][136];   // [k2][n], stride 136 -> conflict-free frags
    const int t    = threadIdx.x;
    const int warp = t >> 5;
    const int lane = t & 31;
    const int gid  = lane >> 2;        // 0..7
    const int tid  = lane & 3;         // 0..3
    const int wr   = warp * 16;
    const long rowBase = (long)blockIdx.x * 128;

    float c[16][4];
    #pragma unroll
    for (int nt = 0; nt < 16; nt++) {
        int col = nt*8 + 2*tid;
        float bv0 = biasRow ? biasRow[col]     : 0.f;
        float bv1 = biasRow ? biasRow[col + 1] : 0.f;
        c[nt][0] = bv0; c[nt][1] = bv1;
        c[nt][2] = bv0; c[nt][3] = bv1;
    }

    // A load mapping: thread -> (row = t>>1, 8 k's at ak8)
    const int arow = t >> 1;
    const int ak8  = (t & 1) * 8;
    const int ak4  = (t & 1) * 4;      // k2 base
    long arg = rowBase + arow; if (arg >= MR) arg = MR - 1;
    // B load mapping: thread -> (n = t&127, 8 k's at bk8)
    const int bn  = t & 127;
    const int bk8 = (t >> 7) * 8;
    const int bk4 = (t >> 7) * 4;

    // prefetch chunk 0
    float4 av0 = *(const float4*)(A + arg*FD + ak8);
    float4 av1 = *(const float4*)(A + arg*FD + ak8 + 4);
    float bp[8];
    #pragma unroll
    for (int j = 0; j < 8; j++) bp[j] = B[(size_t)(bk8 + j)*FD + bn];

    for (int kc = 0; kc < 8; kc++) {
        unsigned h, l;
        packbf(av0.x, av0.y, h, l); Ah[ak4+0][arow] = h; Al[ak4+0][arow] = l;
        packbf(av0.z, av0.w, h, l); Ah[ak4+1][arow] = h; Al[ak4+1][arow] = l;
        packbf(av1.x, av1.y, h, l); Ah[ak4+2][arow] = h; Al[ak4+2][arow] = l;
        packbf(av1.z, av1.w, h, l); Ah[ak4+3][arow] = h; Al[ak4+3][arow] = l;
        packbf(bp[0], bp[1], h, l); Bh[bk4+0][bn] = h; Bl[bk4+0][bn] = l;
        packbf(bp[2], bp[3], h, l); Bh[bk4+1][bn] = h; Bl[bk4+1][bn] = l;
        packbf(bp[4], bp[5], h, l); Bh[bk4+2][bn] = h; Bl[bk4+2][bn] = l;
        packbf(bp[6], bp[7], h, l); Bh[bk4+3][bn] = h; Bl[bk4+3][bn] = l;
        __syncthreads();

        // prefetch next chunk while computing
        if (kc + 1 < 8) {
            av0 = *(const float4*)(A + arg*FD + (kc+1)*16 + ak8);
            av1 = *(const float4*)(A + arg*FD + (kc+1)*16 + ak8 + 4);
            #pragma unroll
            for (int j = 0; j < 8; j++)
                bp[j] = B[(size_t)((kc+1)*16 + bk8 + j)*FD + bn];
        }

        unsigned ah0 = Ah[tid    ][wr + gid    ];
        unsigned ah1 = Ah[tid    ][wr + gid + 8];
        unsigned ah2 = Ah[tid + 4][wr + gid    ];
        unsigned ah3 = Ah[tid + 4][wr + gid + 8];
        unsigned al0 = Al[tid    ][wr + gid    ];
        unsigned al1 = Al[tid    ][wr + gid + 8];
        unsigned al2 = Al[tid + 4][wr + gid    ];
        unsigned al3 = Al[tid + 4][wr + gid + 8];
        #pragma unroll
        for (int nt = 0; nt < 16; nt++) {
            unsigned bh0 = Bh[tid    ][nt*8 + gid];
            unsigned bh1 = Bh[tid + 4][nt*8 + gid];
            unsigned bl0 = Bl[tid    ][nt*8 + gid];
            unsigned bl1 = Bl[tid + 4][nt*8 + gid];
            MMA_BF16(c[nt], al0,al1,al2,al3, bh0,bh1);
            MMA_BF16(c[nt], ah0,ah1,ah2,ah3, bl0,bl1);
            MMA_BF16(c[nt], ah0,ah1,ah2,ah3, bh0,bh1);
        }
        __syncthreads();
    }

    long crow0 = rowBase + wr + gid;
    long crow1 = crow0 + 8;
    #pragma unroll
    for (int nt = 0; nt < 16; nt++) {
        int col = nt*8 + 2*tid;
        if (crow0 < MR) *(float2*)(C + crow0*FD + col) = make_float2(c[nt][0], c[nt][1]);
        if (crow1 < MR) *(float2*)(C + crow1*FD + col) = make_float2(c[nt][2], c[nt][3]);
    }
}

// ---------------- CSR aggregation + fused ReLU + BN stats (no shared atomics) ----------------
// H[b,n] = relu(dinv[n]^2*A[b,n] + bias + sum_e norm[e]*A[b,src[e]])
__global__ __launch_bounds__(256) void k_agg(const float* __restrict__ A,
                                             float* __restrict__ H,
                                             const float* __restrict__ bias,
                                             int statoff) {
    __shared__ float ss[8][256];   // [warp][0:128 sum | 128:256 sumsq]
    int warp = threadIdx.x >> 5;
    int lane = threadIdx.x & 31;
    int n = blockIdx.x * 8 + warp;
    int b = blockIdx.y;

    float4 acc = make_float4(0.f, 0.f, 0.f, 0.f);
    if (n < NN) {
        const float4* Ab = (const float4*)(A + (size_t)b*NN*FD);
        float d = g_dinv[n];
        float sn = d * d;
        float4 v   = Ab[(size_t)n*32 + lane];
        float4 bvv = ((const float4*)bias)[lane];
        acc.x = fmaf(sn, v.x, bvv.x);
        acc.y = fmaf(sn, v.y, bvv.y);
        acc.z = fmaf(sn, v.z, bvv.z);
        acc.w = fmaf(sn, v.w, bvv.w);

        int j = g_rowptr[n];
        const int e = g_rowptr[n + 1];
        for (; j + 1 < e; j += 2) {
            int sA = g_esrc[j],   sB2 = g_esrc[j+1];
            float nA = g_enorm[j], nB = g_enorm[j+1];
            float4 vA = Ab[(size_t)sA*32 + lane];
            float4 vB = Ab[(size_t)sB2*32 + lane];
            acc.x = fmaf(nA, vA.x, acc.x); acc.y = fmaf(nA, vA.y, acc.y);
            acc.z = fmaf(nA, vA.z, acc.z); acc.w = fmaf(nA, vA.w, acc.w);
            acc.x = fmaf(nB, vB.x, acc.x); acc.y = fmaf(nB, vB.y, acc.y);
            acc.z = fmaf(nB, vB.z, acc.z); acc.w = fmaf(nB, vB.w, acc.w);
        }
        if (j < e) {
            int sA = g_esrc[j];
            float nA = g_enorm[j];
            float4 vA = Ab[(size_t)sA*32 + lane];
            acc.x = fmaf(nA, vA.x, acc.x); acc.y = fmaf(nA, vA.y, acc.y);
            acc.z = fmaf(nA, vA.z, acc.z); acc.w = fmaf(nA, vA.w, acc.w);
        }
        acc.x = fmaxf(acc.x, 0.f); acc.y = fmaxf(acc.y, 0.f);
        acc.z = fmaxf(acc.z, 0.f); acc.w = fmaxf(acc.w, 0.f);
        ((float4*)(H + ((size_t)b*NN + n)*FD))[lane] = acc;
    }
    // covering writes: every warp fills its full row (zeros if inactive)
    *(float4*)&ss[warp][lane*4]       = acc;
    *(float4*)&ss[warp][128 + lane*4] = make_float4(acc.x*acc.x, acc.y*acc.y,
                                                    acc.z*acc.z, acc.w*acc.w);
    __syncthreads();
    int t = threadIdx.x;   // 0..255 -> stat index
    float s = ss[0][t] + ss[1][t] + ss[2][t] + ss[3][t]
            + ss[4][t] + ss[5][t] + ss[6][t] + ss[7][t];
    atomicAdd(&g_stats[statoff + t], s);
}

// ---------------- fold BN1 into W2: W2' = a1⊙W2, cw2 = c1@W2 ----------------
__global__ void k_fin1(const float* __restrict__ W2, const float* __restrict__ g1,
                       const float* __restrict__ be1) {
    __shared__ float a[FD], c[FD];
    int t = threadIdx.x;   // 128
    float inv = 1.0f / (float)MR;
    float mu  = g_stats[t] * inv;
    float var = g_stats[128 + t] * inv - mu*mu;
    float av  = g1[t] * rsqrtf(var + 1e-5f);
    a[t] = av; c[t] = be1[t] - mu*av;
    __syncthreads();
    float acc = 0.f;
    for (int f = 0; f < FD; f++) {
        float w = W2[f*FD + t];
        g_W2p[f*FD + t] = a[f]*w;
        acc = fmaf(c[f], w, acc);
    }
    g_cw2[t] = acc;
}

// ---------------- fold BN2 into Wc: Wc' = a2⊙Wc, bc' = bc + c2@Wc ----------------
__global__ void k_fin2(const float* __restrict__ Wc, const float* __restrict__ bc,
                       const float* __restrict__ g2, const float* __restrict__ be2) {
    __shared__ float a[FD], c[FD];
    int t = threadIdx.x;   // 128
    float inv = 1.0f / (float)MR;
    float mu  = g_stats[256 + t] * inv;
    float var = g_stats[384 + t] * inv - mu*mu;
    float av  = g2[t] * rsqrtf(var + 1e-5f);
    a[t] = av; c[t] = be2[t] - mu*av;
    __syncthreads();
    if (t < NOUT) {
        float acc = bc[t];
        for (int f = 0; f < FD; f++) {
            float w = Wc[f*NOUT + t];
            g_Wcp[f*NOUT + t] = a[f]*w;
            acc = fmaf(c[f], w, acc);
        }
        g_bcp[t] = acc;
    }
}

// ---------------- output head: out = H @ Wc' + bc' (H already relu'd) ----------------
__global__ void k_out(float* __restrict__ out) {
    __shared__ float Ws[FD*NOUT];
    __shared__ float Hs[8][FD];
    int t = threadIdx.x;   // 128
    #pragma unroll
    for (int i = 0; i < 16; i++) Ws[i*128 + t] = g_Wcp[i*128 + t];
    long rb = (long)blockIdx.x * 8;
    #pragma unroll
    for (int i = 0; i < 8; i++) {
        long r = rb + i;
        Hs[i][t] = (r < MR) ? g_bufH[r*FD + t] : 0.f;
    }
    __syncthreads();
    int rl = t >> 4, c = t & 15;
    float acc = g_bcp[c];
    #pragma unroll 8
    for (int f = 0; f < FD; f++) acc = fmaf(Hs[rl][f], Ws[f*NOUT + c], acc);
    long r = rb + rl;
    if (r < MR) out[r*NOUT + c] = acc;
}

// ---------------- launcher ----------------
extern "C" void kernel_launch(void* const* d_in, const int* in_sizes, int n_in,
                              void* d_out, int out_size) {
    const float* x   = (const float*)d_in[0];
    const int*   ei  = (const int*)  d_in[1];
    const float* ewp = (const float*)d_in[2];
    const float* W1  = (const float*)d_in[3];
    const float* b1  = (const float*)d_in[4];
    const float* W2  = (const float*)d_in[5];
    const float* b2  = (const float*)d_in[6];
    const float* g1  = (const float*)d_in[7];
    const float* be1 = (const float*)d_in[8];
    const float* g2  = (const float*)d_in[9];
    const float* be2 = (const float*)d_in[10];
    const float* Wc  = (const float*)d_in[11];
    const float* bc  = (const float*)d_in[12];
    float* out = (float*)d_out;

    float *bufA, *bufH, *W2p, *cw2;
    cudaGetSymbolAddress((void**)&bufA, g_bufA);
    cudaGetSymbolAddress((void**)&bufH, g_bufH);
    cudaGetSymbolAddress((void**)&W2p,  g_W2p);
    cudaGetSymbolAddress((void**)&cw2,  g_cw2);

    const int gemmBlocks = (MR + 127) / 128;          // 782
    const dim3 aggGrid((NN + 7) / 8, NB);             // 6250 x 2

    // prep + CSR build (shared by both layers/batches)
    k_init<<<(NN + 255)/256, 256>>>();
    k_deghist<<<(NE + 255)/256, 256>>>(ei, ewp);
    k_dinv<<<(NN + 255)/256, 256>>>();
    k_scan1<<<SB, 1024>>>();
    k_scan2<<<1, 64>>>();
    k_scan3<<<SB, 1024>>>();
    k_fill<<<(NE + 255)/256, 256>>>(ei, ewp);

    // Layer 1
    k_gemm<<<gemmBlocks, 256>>>(x, W1, bufA, nullptr);
    k_agg<<<aggGrid, 256>>>(bufA, bufH, b1, 0);
    k_fin1<<<1, 128>>>(W2, g1, be1);

    // Layer 2 (H already relu'd; BN1 folded into W2p/cw2)
    k_gemm<<<gemmBlocks, 256>>>(bufH, W2p, bufA, cw2);
    k_agg<<<aggGrid, 256>>>(bufA, bufH, b2, 256);
    k_fin2<<<1, 128>>>(Wc, bc, g2, be2);

    // Head (H already relu'd; BN2 folded into Wcp/bcp)
    k_out<<<(MR + 7)/8, 128>>>(out);
}

// round 8
// speedup vs baseline: 1.2413x; 1.0400x over previous
#include <cuda_runtime.h>
#include <math.h>
#include <stdint.h>

#define NB 2
#define NN 50000
#define NE 640000
#define FD 128
#define NOUT 16
#define MR (NB*NN)   // 100000 rows
#define SB 49        // scan blocks (49*1024 >= NN)

// ---------------- device scratch (allocation-free) ----------------
__device__ __align__(256) float g_dinv[NN];
__device__ __align__(256) float g_deg[NN];
__device__ __align__(256) int   g_cnt[NN];
__device__ __align__(256) int   g_cur[NN];
__device__ __align__(256) int   g_rowptr[NN + 1];
__device__ __align__(256) int   g_bsum[SB];
__device__ __align__(256) int   g_boff[SB];
__device__ __align__(256) int   g_esrc[NE];     // src ids sorted by dst
__device__ __align__(256) float g_enorm[NE];    // norm sorted by dst
__device__ __align__(256) float g_bufA[(size_t)MR*FD];   // xw / xw2
__device__ __align__(256) float g_bufH[(size_t)MR*FD];   // relu(aggregated h)
__device__ __align__(256) float g_stats[512];            // sum/sumsq for 2 layers
__device__ __align__(256) float g_W2p[FD*FD];            // a1 ⊙ W2
__device__ __align__(256) float g_cw2[FD];               // c1 @ W2
__device__ __align__(256) float g_Wcp[FD*NOUT];          // a2 ⊙ Wc
__device__ __align__(256) float g_bcp[NOUT];             // bc + c2 @ Wc
// pre-split weight images: BH/BL[k2*128 + n] = bf16x2 of (W[2k2][n], W[2k2+1][n]) hi/lo
__device__ __align__(256) unsigned g_BH1[8192];
__device__ __align__(256) unsigned g_BL1[8192];
__device__ __align__(256) unsigned g_BH2[8192];
__device__ __align__(256) unsigned g_BL2[8192];

// bf16 hi/lo split, packed as bf16x2 (lower half = f0/even-k)
__device__ __forceinline__ void packbf(float f0, float f1, unsigned &hi, unsigned &lo) {
    asm("cvt.rn.bf16x2.f32 %0, %1, %2;" : "=r"(hi) : "f"(f1), "f"(f0));
    float h0 = __uint_as_float(hi << 16);
    float h1 = __uint_as_float(hi & 0xffff0000u);
    asm("cvt.rn.bf16x2.f32 %0, %1, %2;" : "=r"(lo) : "f"(f1 - h1), "f"(f0 - h0));
}
#define MMA_BF16(C, A0,A1,A2,A3, B0,B1) \
    asm volatile( \
        "mma.sync.aligned.m16n8k16.row.col.f32.bf16.bf16.f32 " \
        "{%0,%1,%2,%3}, {%4,%5,%6,%7}, {%8,%9}, {%0,%1,%2,%3};" \
        : "+f"(C[0]), "+f"(C[1]), "+f"(C[2]), "+f"(C[3]) \
        : "r"(A0), "r"(A1), "r"(A2), "r"(A3), "r"(B0), "r"(B1))

// ---------------- prep: init, degree+histogram, dinv ----------------
__global__ void k_init() {
    int i = blockIdx.x*blockDim.x + threadIdx.x;
    if (i < NN) { g_deg[i] = 1.0f; g_cnt[i] = 0; }   // self-loop weight = 1
    if (i < 512) g_stats[i] = 0.0f;
}

__global__ void k_deghist(const int* __restrict__ ei, const float* __restrict__ ewp) {
    int e = blockIdx.x*blockDim.x + threadIdx.x;
    if (e >= NE) return;
    int dst = ei[NE + e];
    atomicAdd(&g_deg[dst], expf(ewp[e]));
    atomicAdd(&g_cnt[dst], 1);
}

__global__ void k_dinv() {
    int i = blockIdx.x*blockDim.x + threadIdx.x;
    if (i < NN) g_dinv[i] = rsqrtf(g_deg[i]);   // deg >= 1 always
}

// ---------------- parallel 3-phase exclusive scan over g_cnt ----------------
__global__ __launch_bounds__(1024) void k_scan1() {
    __shared__ int sh[1024];
    const int t = threadIdx.x;
    const int i = blockIdx.x * 1024 + t;
    int v = (i < NN) ? g_cnt[i] : 0;
    sh[t] = v;
    __syncthreads();
    #pragma unroll
    for (int off = 1; off < 1024; off <<= 1) {
        int x = (t >= off) ? sh[t - off] : 0;
        __syncthreads();
        sh[t] += x;
        __syncthreads();
    }
    if (i < NN) g_rowptr[i] = sh[t] - v;
    if (t == 1023) g_bsum[blockIdx.x] = sh[1023];
}

__global__ void k_scan2() {
    __shared__ int s[SB];
    int t = threadIdx.x;
    if (t < SB) s[t] = g_bsum[t];
    __syncthreads();
    if (t == 0) {
        int run = 0;
        for (int i = 0; i < SB; i++) { int v = s[i]; s[i] = run; run += v; }
    }
    __syncthreads();
    if (t < SB) g_boff[t] = s[t];
}

__global__ __launch_bounds__(1024) void k_scan3() {
    const int i = blockIdx.x * 1024 + threadIdx.x;
    if (i < NN) {
        int v = g_rowptr[i] + g_boff[blockIdx.x];
        g_rowptr[i] = v;
        g_cur[i]    = v;
    }
    if (i == 0) g_rowptr[NN] = NE;
}

// ---------------- fill CSR buckets (src + norm, sorted by dst) ----------------
__global__ void k_fill(const int* __restrict__ ei, const float* __restrict__ ewp) {
    int e = blockIdx.x*blockDim.x + threadIdx.x;
    if (e >= NE) return;
    int src = ei[e], dst = ei[NE + e];
    int p = atomicAdd(&g_cur[dst], 1);
    g_esrc[p]  = src;
    g_enorm[p] = g_dinv[src] * expf(ewp[e]) * g_dinv[dst];
}

// ---------------- weight split/transpose: BH/BL[k2*128+n] ----------------
__global__ void k_wsplit(const float* __restrict__ W, unsigned* __restrict__ BH,
                         unsigned* __restrict__ BL) {
    int idx = blockIdx.x*256 + threadIdx.x;   // 8192 bf16x2 words
    if (idx >= 8192) return;
    int k2 = idx >> 7;
    int n  = idx & 127;
    float f0 = W[(size_t)(2*k2)*FD + n];
    float f1 = W[(size_t)(2*k2+1)*FD + n];
    unsigned h, l; packbf(f0, f1, h, l);
    BH[idx] = h;
    BL[idx] = l;
}

// ---------------- sync-free 3-term split-bf16 MMA GEMM ----------------
// C[MR,128] = A[MR,128] @ W[128,128] (+ biasRow); D = Al*Bh + Ah*Bl + Ah*Bh
#define BSTRIDE 136
#define SM_GEMM_BYTES (2 * 64 * BSTRIDE * 4)   // 69632

__global__ __launch_bounds__(256, 2)
void k_gemm_mma(const float* __restrict__ A, float* __restrict__ C,
                const float* __restrict__ biasRow,
                const unsigned* __restrict__ BH, const unsigned* __restrict__ BL) {
    extern __shared__ unsigned sm[];
    unsigned* sBH = sm;                    // [64][136]
    unsigned* sBL = sm + 64*BSTRIDE;
    const int t    = threadIdx.x;
    const int warp = t >> 5;
    const int lane = t & 31;
    const int gid  = lane >> 2;            // 0..7
    const int tid  = lane & 3;             // 0..3
    const int wr   = warp * 16;
    const long rowBase = (long)blockIdx.x * 128;

    // stage both B images into smem (once; stride 136 rows for conflict-free frags)
    {
        const float4* srcH = (const float4*)BH;
        const float4* srcL = (const float4*)BL;
        float4* dH = (float4*)sBH;
        float4* dL = (float4*)sBL;
        #pragma unroll
        for (int i = 0; i < 8; i++) {
            int idx = t + 256*i;           // 2048 float4s
            int k2 = idx >> 5, n4 = idx & 31;
            dH[k2*34 + n4] = srcH[idx];
            dL[k2*34 + n4] = srcL[idx];
        }
    }

    float c[16][4];
    #pragma unroll
    for (int nt = 0; nt < 16; nt++) {
        int col = nt*8 + 2*tid;
        float bv0 = biasRow ? biasRow[col]     : 0.f;
        float bv1 = biasRow ? biasRow[col + 1] : 0.f;
        c[nt][0] = bv0; c[nt][1] = bv1;
        c[nt][2] = bv0; c[nt][3] = bv1;
    }

    long r0 = rowBase + wr + gid;  if (r0 >= MR) r0 = MR - 1;
    long r1 = r0 + 8;              if (r1 >= MR) r1 = MR - 1;
    const float* A0 = A + r0*FD;
    const float* A1 = A + r1*FD;

    __syncthreads();

    // prefetch kc=0 A fragments
    float2 l0 = *(const float2*)(A0 + 2*tid);
    float2 l1 = *(const float2*)(A1 + 2*tid);
    float2 l2 = *(const float2*)(A0 + 2*tid + 8);
    float2 l3 = *(const float2*)(A1 + 2*tid + 8);

    #pragma unroll
    for (int kc = 0; kc < 8; kc++) {
        unsigned ah0, al0, ah1, al1, ah2, al2, ah3, al3;
        packbf(l0.x, l0.y, ah0, al0);
        packbf(l1.x, l1.y, ah1, al1);
        packbf(l2.x, l2.y, ah2, al2);
        packbf(l3.x, l3.y, ah3, al3);
        if (kc + 1 < 8) {
            int ko = (kc + 1) * 16;
            l0 = *(const float2*)(A0 + ko + 2*tid);
            l1 = *(const float2*)(A1 + ko + 2*tid);
            l2 = *(const float2*)(A0 + ko + 2*tid + 8);
            l3 = *(const float2*)(A1 + ko + 2*tid + 8);
        }
        const unsigned* ph0 = sBH + (kc*8 + tid    )*BSTRIDE + gid;
        const unsigned* ph1 = sBH + (kc*8 + tid + 4)*BSTRIDE + gid;
        const unsigned* pl0 = sBL + (kc*8 + tid    )*BSTRIDE + gid;
        const unsigned* pl1 = sBL + (kc*8 + tid + 4)*BSTRIDE + gid;
        #pragma unroll
        for (int nt = 0; nt < 16; nt++) {
            unsigned bh0 = ph0[nt*8], bh1 = ph1[nt*8];
            unsigned bl0 = pl0[nt*8], bl1 = pl1[nt*8];
            MMA_BF16(c[nt], al0, al1, al2, al3, bh0, bh1);
            MMA_BF16(c[nt], ah0, ah1, ah2, ah3, bl0, bl1);
            MMA_BF16(c[nt], ah0, ah1, ah2, ah3, bh0, bh1);
        }
    }

    long crow0 = rowBase + wr + gid;
    long crow1 = crow0 + 8;
    #pragma unroll
    for (int nt = 0; nt < 16; nt++) {
        int col = nt*8 + 2*tid;
        if (crow0 < MR) *(float2*)(C + crow0*FD + col) = make_float2(c[nt][0], c[nt][1]);
        if (crow1 < MR) *(float2*)(C + crow1*FD + col) = make_float2(c[nt][2], c[nt][3]);
    }
}

// ---------------- CSR aggregation + fused ReLU + BN stats (no shared atomics) ----------------
__global__ __launch_bounds__(256) void k_agg(const float* __restrict__ A,
                                             float* __restrict__ H,
                                             const float* __restrict__ bias,
                                             int statoff) {
    __shared__ float ss[8][256];
    int warp = threadIdx.x >> 5;
    int lane = threadIdx.x & 31;
    int n = blockIdx.x * 8 + warp;
    int b = blockIdx.y;

    float4 acc = make_float4(0.f, 0.f, 0.f, 0.f);
    if (n < NN) {
        const float4* Ab = (const float4*)(A + (size_t)b*NN*FD);
        float d = g_dinv[n];
        float sn = d * d;
        float4 v   = Ab[(size_t)n*32 + lane];
        float4 bvv = ((const float4*)bias)[lane];
        acc.x = fmaf(sn, v.x, bvv.x);
        acc.y = fmaf(sn, v.y, bvv.y);
        acc.z = fmaf(sn, v.z, bvv.z);
        acc.w = fmaf(sn, v.w, bvv.w);

        int j = g_rowptr[n];
        const int e = g_rowptr[n + 1];
        for (; j + 1 < e; j += 2) {
            int sA = g_esrc[j],   sB2 = g_esrc[j+1];
            float nA = g_enorm[j], nB = g_enorm[j+1];
            float4 vA = Ab[(size_t)sA*32 + lane];
            float4 vB = Ab[(size_t)sB2*32 + lane];
            acc.x = fmaf(nA, vA.x, acc.x); acc.y = fmaf(nA, vA.y, acc.y);
            acc.z = fmaf(nA, vA.z, acc.z); acc.w = fmaf(nA, vA.w, acc.w);
            acc.x = fmaf(nB, vB.x, acc.x); acc.y = fmaf(nB, vB.y, acc.y);
            acc.z = fmaf(nB, vB.z, acc.z); acc.w = fmaf(nB, vB.w, acc.w);
        }
        if (j < e) {
            int sA = g_esrc[j];
            float nA = g_enorm[j];
            float4 vA = Ab[(size_t)sA*32 + lane];
            acc.x = fmaf(nA, vA.x, acc.x); acc.y = fmaf(nA, vA.y, acc.y);
            acc.z = fmaf(nA, vA.z, acc.z); acc.w = fmaf(nA, vA.w, acc.w);
        }
        acc.x = fmaxf(acc.x, 0.f); acc.y = fmaxf(acc.y, 0.f);
        acc.z = fmaxf(acc.z, 0.f); acc.w = fmaxf(acc.w, 0.f);
        ((float4*)(H + ((size_t)b*NN + n)*FD))[lane] = acc;
    }
    *(float4*)&ss[warp][lane*4]       = acc;
    *(float4*)&ss[warp][128 + lane*4] = make_float4(acc.x*acc.x, acc.y*acc.y,
                                                    acc.z*acc.z, acc.w*acc.w);
    __syncthreads();
    int t = threadIdx.x;
    float s = ss[0][t] + ss[1][t] + ss[2][t] + ss[3][t]
            + ss[4][t] + ss[5][t] + ss[6][t] + ss[7][t];
    atomicAdd(&g_stats[statoff + t], s);
}

// ---------------- fold BN1 into W2: W2' = a1⊙W2, cw2 = c1@W2 ----------------
__global__ void k_fin1(const float* __restrict__ W2, const float* __restrict__ g1,
                       const float* __restrict__ be1) {
    __shared__ float a[FD], c[FD];
    int t = threadIdx.x;   // 128
    float inv = 1.0f / (float)MR;
    float mu  = g_stats[t] * inv;
    float var = g_stats[128 + t] * inv - mu*mu;
    float av  = g1[t] * rsqrtf(var + 1e-5f);
    a[t] = av; c[t] = be1[t] - mu*av;
    __syncthreads();
    float acc = 0.f;
    for (int f = 0; f < FD; f++) {
        float w = W2[f*FD + t];
        g_W2p[f*FD + t] = a[f]*w;
        acc = fmaf(c[f], w, acc);
    }
    g_cw2[t] = acc;
}

// ---------------- fold BN2 into Wc: Wc' = a2⊙Wc, bc' = bc + c2@Wc ----------------
__global__ void k_fin2(const float* __restrict__ Wc, const float* __restrict__ bc,
                       const float* __restrict__ g2, const float* __restrict__ be2) {
    __shared__ float a[FD], c[FD];
    int t = threadIdx.x;   // 128
    float inv = 1.0f / (float)MR;
    float mu  = g_stats[256 + t] * inv;
    float var = g_stats[384 + t] * inv - mu*mu;
    float av  = g2[t] * rsqrtf(var + 1e-5f);
    a[t] = av; c[t] = be2[t] - mu*av;
    __syncthreads();
    if (t < NOUT) {
        float acc = bc[t];
        for (int f = 0; f < FD; f++) {
            float w = Wc[f*NOUT + t];
            g_Wcp[f*NOUT + t] = a[f]*w;
            acc = fmaf(c[f], w, acc);
        }
        g_bcp[t] = acc;
    }
}

// ---------------- output head: out = H @ Wc' + bc' (H already relu'd) ----------------
__global__ void k_out(float* __restrict__ out) {
    __shared__ float Ws[FD*NOUT];
    __shared__ float Hs[8][FD];
    int t = threadIdx.x;   // 128
    #pragma unroll
    for (int i = 0; i < 16; i++) Ws[i*128 + t] = g_Wcp[i*128 + t];
    long rb = (long)blockIdx.x * 8;
    #pragma unroll
    for (int i = 0; i < 8; i++) {
        long r = rb + i;
        Hs[i][t] = (r < MR) ? g_bufH[r*FD + t] : 0.f;
    }
    __syncthreads();
    int rl = t >> 4, c = t & 15;
    float acc = g_bcp[c];
    #pragma unroll 8
    for (int f = 0; f < FD; f++) acc = fmaf(Hs[rl][f], Ws[f*NOUT + c], acc);
    long r = rb + rl;
    if (r < MR) out[r*NOUT + c] = acc;
}

// ---------------- launcher ----------------
extern "C" void kernel_launch(void* const* d_in, const int* in_sizes, int n_in,
                              void* d_out, int out_size) {
    const float* x   = (const float*)d_in[0];
    const int*   ei  = (const int*)  d_in[1];
    const float* ewp = (const float*)d_in[2];
    const float* W1  = (const float*)d_in[3];
    const float* b1  = (const float*)d_in[4];
    const float* W2  = (const float*)d_in[5];
    const float* b2  = (const float*)d_in[6];
    const float* g1  = (const float*)d_in[7];
    const float* be1 = (const float*)d_in[8];
    const float* g2  = (const float*)d_in[9];
    const float* be2 = (const float*)d_in[10];
    const float* Wc  = (const float*)d_in[11];
    const float* bc  = (const float*)d_in[12];
    float* out = (float*)d_out;

    float *bufA, *bufH, *W2p, *cw2;
    unsigned *bh1, *bl1, *bh2, *bl2;
    cudaGetSymbolAddress((void**)&bufA, g_bufA);
    cudaGetSymbolAddress((void**)&bufH, g_bufH);
    cudaGetSymbolAddress((void**)&W2p,  g_W2p);
    cudaGetSymbolAddress((void**)&cw2,  g_cw2);
    cudaGetSymbolAddress((void**)&bh1,  g_BH1);
    cudaGetSymbolAddress((void**)&bl1,  g_BL1);
    cudaGetSymbolAddress((void**)&bh2,  g_BH2);
    cudaGetSymbolAddress((void**)&bl2,  g_BL2);

    cudaFuncSetAttribute(k_gemm_mma, cudaFuncAttributeMaxDynamicSharedMemorySize, SM_GEMM_BYTES);

    const int gemmBlocks = (MR + 127) / 128;          // 782
    const dim3 aggGrid((NN + 7) / 8, NB);             // 6250 x 2

    // prep + CSR build (shared by both layers/batches)
    k_init<<<(NN + 255)/256, 256>>>();
    k_deghist<<<(NE + 255)/256, 256>>>(ei, ewp);
    k_dinv<<<(NN + 255)/256, 256>>>();
    k_scan1<<<SB, 1024>>>();
    k_scan2<<<1, 64>>>();
    k_scan3<<<SB, 1024>>>();
    k_fill<<<(NE + 255)/256, 256>>>(ei, ewp);
    k_wsplit<<<32, 256>>>(W1, bh1, bl1);

    // Layer 1
    k_gemm_mma<<<gemmBlocks, 256, SM_GEMM_BYTES>>>(x, bufA, nullptr, bh1, bl1);
    k_agg<<<aggGrid, 256>>>(bufA, bufH, b1, 0);
    k_fin1<<<1, 128>>>(W2, g1, be1);
    k_wsplit<<<32, 256>>>(W2p, bh2, bl2);

    // Layer 2 (H already relu'd; BN1 folded into W2p/cw2)
    k_gemm_mma<<<gemmBlocks, 256, SM_GEMM_BYTES>>>(bufH, bufA, cw2, bh2, bl2);
    k_agg<<<aggGrid, 256>>>(bufA, bufH, b2, 256);
    k_fin2<<<1, 128>>>(Wc, bc, g2, be2);

    // Head (H already relu'd; BN2 folded into Wcp/bcp)
    k_out<<<(MR + 7)/8, 128>>>(out);
}